// round 2
// baseline (speedup 1.0000x reference)
#include <cuda_runtime.h>
#include <cstdint>

#define HH 128
#define NP 16384            // HH*HH pixels
#define GC 13               // grid cells per color axis
#define NC (GC*GC*GC)       // 2197 cells
#define CELLW 21.0f
#define CAP 64              // max kept neighbors per pixel
#define ETH 16.0f           // keep K >= exp(-16); dropped tail mass ~2e-7
#define INV_TA (1.0f/160.0f)
#define INV_TB (1.0f/3.0f)
#define INV_TG (1.0f/3.0f)
#define NBLK 128            // grid size of grid-synced kernels (<< 148 SMs)

// ---------------- device scratch ----------------
__device__ float  g_G[HH*HH];
__device__ float  g_rs[HH];
__device__ int    g_cellCnt[NC];
__device__ int    g_cellStart[NC+1];
__device__ int    g_cursor[NC];
__device__ int    g_sidx[NP];
__device__ float4 g_sfA[NP];
__device__ float2 g_sfB[NP];
__device__ float2 g_ell[CAP*NP];    // slot-major: (.x=K, .y=bitcast idx)
__device__ int    g_ellCnt[NP];
__device__ float  g_blNorm[NP];
__device__ float  g_sm0[2*NP];      // double-buffered softmax ch0
__device__ float  g_T[2*NP];        // double-buffered spatial row-pass

// ---------------- software grid barrier (co-resident grids only) ----------
__device__ unsigned g_barGen = 0;
__device__ unsigned g_barCnt = 0;

__device__ __forceinline__ void gridbar() {
    __threadfence();              // publish this thread's writes device-wide
    __syncthreads();              // whole block done + fenced
    if (threadIdx.x == 0) {
        unsigned gen = atomicAdd(&g_barGen, 0u);   // read current generation
        unsigned arrived = atomicAdd(&g_barCnt, 1u);
        if (arrived == NBLK - 1u) {
            g_barCnt = 0;
            __threadfence();
            atomicAdd(&g_barGen, 1u);              // release
        } else {
            while (atomicAdd(&g_barGen, 0u) == gen) { __nanosleep(64); }
        }
        __threadfence();          // acquire
    }
    __syncthreads();
}

__device__ __forceinline__ int clampCell(float v) {
    int c = (int)(v * (1.0f/CELLW));
    return c < 0 ? 0 : (c > GC-1 ? GC-1 : c);
}
__device__ __forceinline__ int cellOf(const float* __restrict__ rgb, int p) {
    return (clampCell(rgb[3*p+2])*GC + clampCell(rgb[3*p+1]))*GC + clampCell(rgb[3*p]);
}

// ---------------- setup: gauss + count + scan + scatter + cellsort --------
__global__ void k_setup(const float* __restrict__ rgb) {
    int i = blockIdx.x, j = threadIdx.x;
    int tid = i*HH + j;

    // phase A: Gaussian matrix + row sums; zero cell counts
    {
        float d = (float)(i - j) * INV_TG;
        float g = __expf(-0.5f * d * d);
        g_G[tid] = g;
        __shared__ float s[HH];
        s[j] = g; __syncthreads();
        for (int o = 64; o > 0; o >>= 1) { if (j < o) s[j] += s[j+o]; __syncthreads(); }
        if (j == 0) g_rs[i] = s[0];
        if (tid < NC) g_cellCnt[tid] = 0;
    }
    gridbar();

    // phase B: count pixels per color cell
    atomicAdd(&g_cellCnt[cellOf(rgb, tid)], 1);
    gridbar();

    // phase C: exclusive scan over 2197 cells (block 0 only)
    if (i == 0) {
        __shared__ int part[HH];
        const int CH = 18;                         // 128*18 = 2304 >= 2197
        int base = j*CH, s = 0, loc[CH];
        for (int k = 0; k < CH; k++) {
            int c = base + k; int v = (c < NC) ? g_cellCnt[c] : 0;
            loc[k] = v; s += v;
        }
        part[j] = s; __syncthreads();
        if (j == 0) {
            int acc = 0;
            for (int b = 0; b < HH; b++) { int v = part[b]; part[b] = acc; acc += v; }
            g_cellStart[NC] = acc;
        }
        __syncthreads();
        int acc = part[j];
        for (int k = 0; k < CH; k++) {
            int c = base + k;
            if (c < NC) { g_cellStart[c] = acc; g_cursor[c] = acc; }
            acc += loc[k];
        }
    }
    gridbar();

    // phase D: scatter pixel ids into cells
    {
        int slot = atomicAdd(&g_cursor[cellOf(rgb, tid)], 1);
        g_sidx[slot] = tid;
    }
    gridbar();

    // phase E: per-cell insertion sort (determinism) + sorted feature fill
    if (tid < NC) {
        int st = g_cellStart[tid], en = g_cellStart[tid+1];
        for (int a = st + 1; a < en; a++) {
            int v = g_sidx[a]; int k = a - 1;
            while (k >= st && g_sidx[k] > v) { g_sidx[k+1] = g_sidx[k]; k--; }
            g_sidx[k+1] = v;
        }
        for (int s = st; s < en; s++) {
            int p = g_sidx[s];
            int y = p >> 7, x = p & 127;
            g_sfA[s] = make_float4((float)x * INV_TA, (float)y * INV_TA,
                                   rgb[3*p] * INV_TB, rgb[3*p+1] * INV_TB);
            g_sfB[s] = make_float2(rgb[3*p+2] * INV_TB, __int_as_float(p));
        }
    }
}

// ---------------- ELL build: warp per pixel ----------------
__global__ void k_build(const float* __restrict__ rgb) {
    int gtid = blockIdx.x * blockDim.x + threadIdx.x;
    int p = gtid >> 5;
    int lane = threadIdx.x & 31;
    if (p >= NP) return;

    int y = p >> 7, x = p & 127;
    float f0 = (float)x * INV_TA;
    float f1 = (float)y * INV_TA;
    float f2 = rgb[3*p]   * INV_TB;
    float f3 = rgb[3*p+1] * INV_TB;
    float f4 = rgb[3*p+2] * INV_TB;
    int c0 = clampCell(rgb[3*p]);
    int c1 = clampCell(rgb[3*p+1]);
    int c2 = clampCell(rgb[3*p+2]);

    int cnt = 0;
    float norm = 0.0f;
    for (int dz = -1; dz <= 1; dz++) {
        int cz = c2 + dz; if (cz < 0 || cz >= GC) continue;
        for (int dy = -1; dy <= 1; dy++) {
            int cy = c1 + dy; if (cy < 0 || cy >= GC) continue;
            for (int dx = -1; dx <= 1; dx++) {
                int cx = c0 + dx; if (cx < 0 || cx >= GC) continue;
                int cell = (cz*GC + cy)*GC + cx;
                int st = g_cellStart[cell], en = g_cellStart[cell+1];
                for (int s0 = st; s0 < en; s0 += 32) {
                    int s = s0 + lane;
                    bool keep = false; float val = 0.0f; int jdx = 0;
                    if (s < en) {
                        float4 fA = g_sfA[s];
                        float2 fB = g_sfB[s];
                        float d0 = f0 - fA.x, d1 = f1 - fA.y, d2 = f2 - fA.z,
                              d3 = f3 - fA.w, d4 = f4 - fB.x;
                        float e = 0.5f*(d0*d0 + d1*d1 + d2*d2 + d3*d3 + d4*d4);
                        if (e < ETH) { keep = true; val = __expf(-e); jdx = __float_as_int(fB.y); }
                    }
                    unsigned m = __ballot_sync(0xffffffffu, keep);
                    if (keep) {
                        int off = cnt + __popc(m & ((1u << lane) - 1u));
                        if (off < CAP) {
                            g_ell[off*NP + p] = make_float2(val, __int_as_float(jdx));
                            norm += val;
                        }
                    }
                    cnt += __popc(m);
                }
            }
        }
    }
    if (cnt > CAP) cnt = CAP;
    for (int o = 16; o > 0; o >>= 1) norm += __shfl_xor_sync(0xffffffffu, norm, o);
    if (lane == 0) { g_ellCnt[p] = cnt; g_blNorm[p] = norm; }
}

// ---------------- persistent iteration kernel: all 10 iterations ----------
__global__ void k_iter(const float* __restrict__ U,
                       const float* __restrict__ Ws,
                       const float* __restrict__ Wb,
                       const float* __restrict__ Cm,
                       float* __restrict__ out) {
    int r = blockIdx.x, t = threadIdx.x, p = r*HH + t;
    __shared__ float s[HH];
    __shared__ float sg[HH];

    sg[t] = g_G[r*HH + t];                      // G row r (for column pass)
    float invn = 1.0f / (g_rs[r] * g_rs[t]);    // spatial norm reciprocal
    float u0 = U[2*p], u1 = U[2*p+1];
    float ws0 = Ws[0], ws1 = Ws[1], ws2 = Ws[2], ws3 = Ws[3];
    float wb0 = Wb[0], wb1 = Wb[1], wb2 = Wb[2], wb3 = Wb[3];
    float cm0 = Cm[0], cm1 = Cm[1], cm2 = Cm[2], cm3 = Cm[3];
    int   cnt = g_ellCnt[p];
    float bln = g_blNorm[p];

    // prologue: sm from q = U, row pass into buffer 0
    float sm = 1.0f / (1.0f + __expf(u1 - u0));
    g_sm0[p] = sm;
    s[t] = sm;
    __syncthreads();
    {
        float acc = 0.0f;
        #pragma unroll 8
        for (int k = 0; k < HH; k++) acc += s[k] * g_G[k*HH + t];
        g_T[p] = acc;
    }
    gridbar();

    float q0 = u0, q1 = u1;
    for (int it = 0; it < 10; it++) {
        int cur = it & 1, nxt = cur ^ 1;

        // spatial column pass
        float sp = 0.0f;
        const float* Tc = g_T + cur*NP;
        #pragma unroll 8
        for (int j = 0; j < HH; j++) sp += sg[j] * Tc[j*HH + t];
        sp *= invn;

        // bilateral SpMV
        const float* smc = g_sm0 + cur*NP;
        float acc = 0.0f;
        #pragma unroll 4
        for (int k = 0; k < cnt; k++) {
            float2 e = g_ell[k*NP + p];
            acc += e.x * smc[__float_as_int(e.y)];
        }
        float bl = acc / bln;

        float sp1 = 1.0f - sp, bl1 = 1.0f - bl;
        float mp0 = ws0*sp + ws1*sp1 + wb0*bl + wb1*bl1;
        float mp1 = ws2*sp + ws3*sp1 + wb2*bl + wb3*bl1;
        q0 = u0 - (cm0*mp0 + cm1*mp1);
        q1 = u1 - (cm2*mp0 + cm3*mp1);

        if (it < 9) {
            // fused sigmoid + row pass into the other buffer
            sm = 1.0f / (1.0f + __expf(q1 - q0));
            g_sm0[nxt*NP + p] = sm;
            __syncthreads();                    // everyone done reading s? (s unused
            s[t] = sm;                          //  this iter; sync for prior writer)
            __syncthreads();
            float a2 = 0.0f;
            #pragma unroll 8
            for (int k = 0; k < HH; k++) a2 += s[k] * g_G[k*HH + t];
            g_T[nxt*NP + t + r*HH] = a2;
            gridbar();
        }
    }
    out[2*p]   = q0;
    out[2*p+1] = q1;
}

// ---------------- launch ----------------
extern "C" void kernel_launch(void* const* d_in, const int* in_sizes, int n_in,
                              void* d_out, int out_size) {
    const float* U   = (const float*)d_in[0];
    const float* rgb = (const float*)d_in[1];
    const float* Ws  = (const float*)d_in[2];
    const float* Wb  = (const float*)d_in[3];
    const float* Cm  = (const float*)d_in[4];
    float* out = (float*)d_out;

    k_setup<<<NBLK, HH>>>(rgb);
    k_build<<<(NP*32 + 255)/256, 256>>>(rgb);
    k_iter <<<NBLK, HH>>>(U, Ws, Wb, Cm, out);
}

// round 6
// speedup vs baseline: 1.6737x; 1.6737x over previous
#include <cuda_runtime.h>
#include <cstdint>

#define HH 128
#define NP 16384            // HH*HH pixels
#define GC 13               // color-grid cells per axis
#define NC (GC*GC*GC)       // 2197 cells
#define CELLW 21.0f
#define CAP 64              // max kept neighbors per pixel
#define ETH 16.0f           // keep K >= exp(-16); dropped tail ~2e-7
#define INV_TA (1.0f/160.0f)
#define INV_TB (1.0f/3.0f)
#define INV_TG (1.0f/3.0f)
#define NBLK 128            // grid blocks (< 148 SMs -> co-resident, barrier safe)
#define NTHR 512            // threads per block (16 warps)

// ---------------- device scratch ----------------
__device__ float  g_G[HH*HH];
__device__ float  g_rs[HH];
__device__ int    g_cellCnt[NC];
__device__ int    g_cellStart[NC+1];
__device__ int    g_cursor[NC];
__device__ int    g_sidx[NP];
__device__ float4 g_sfA[NP];
__device__ float2 g_sfB[NP];
__device__ float2 g_ell[CAP*NP];     // slot-major: (.x=K, .y=bitcast idx)
__device__ int    g_ellCnt[NP];
__device__ float  g_blNorm[NP];
__device__ float  g_sm0[2*NP];       // double-buffered softmax ch0
__device__ float  g_T[2*NP];         // double-buffered spatial row-pass
__device__ unsigned long long g_barCnt;   // monotonic grid-barrier counter

// ---- grid barrier: fence + atomic arrival, volatile-load polling ---------
__device__ __forceinline__ void gridbar(unsigned long long target) {
    __syncthreads();
    if (threadIdx.x == 0) {
        __threadfence();                                  // release my writes
        atomicAdd(&g_barCnt, 1ULL);                       // arrive
        volatile unsigned long long* c = &g_barCnt;
        while (*c < target) { }                           // plain-read spin
        __threadfence();                                  // acquire others'
    }
    __syncthreads();
}

__device__ __forceinline__ int clampCell(float v) {
    int c = (int)(v * (1.0f/CELLW));
    return c < 0 ? 0 : (c > GC-1 ? GC-1 : c);
}
__device__ __forceinline__ int cellOf(const float* __restrict__ rgb, int p) {
    return (clampCell(rgb[3*p+2])*GC + clampCell(rgb[3*p+1]))*GC + clampCell(rgb[3*p]);
}

// ---------------- init: zero barrier counter + cell counts ----------------
__global__ void k_zero() {
    int t = blockIdx.x * blockDim.x + threadIdx.x;
    if (t == 0) g_barCnt = 0ULL;
    if (t < NC) g_cellCnt[t] = 0;
}

// ---------------- mega-kernel: setup + build + 10 iterations --------------
__global__ void __launch_bounds__(NTHR, 1)
k_crf(const float* __restrict__ U, const float* __restrict__ rgb,
      const float* __restrict__ Ws, const float* __restrict__ Wb,
      const float* __restrict__ Cm, float* __restrict__ out) {
    const int tid  = threadIdx.x;
    const int bid  = blockIdx.x;
    const int gtid = bid * NTHR + tid;          // 0..65535 (4x NP!)
    const int t    = tid & 127;                 // pixel column within row
    const int qq   = tid >> 7;                  // quarter 0..3
    const int r    = bid;                       // image row handled by block
    const int p    = r * HH + t;

    __shared__ float s[HH];        // current row's softmax
    __shared__ float sg[HH];       // G row r
    __shared__ float red1[NTHR];   // reduction scratch A
    __shared__ float red2[NTHR];   // reduction scratch B
    __shared__ int   scnt[HH];     // per-pixel ELL counts
    __shared__ int   spart[256];   // scan scratch

    // ---- phase A: Gaussian matrix + per-cell counts (GUARDED: gtid < NP) ----
    if (gtid < NP) {
        int i = gtid >> 7, j = gtid & 127;
        float d = (float)(i - j) * INV_TG;
        g_G[gtid] = __expf(-0.5f * d * d);
        atomicAdd(&g_cellCnt[cellOf(rgb, gtid)], 1);
    }
    gridbar(1ULL*NBLK);

    // ---- phase B: row sums (block 1) + exclusive scan (block 0) ----
    if (bid == 1 && tid < HH) {
        float acc = 0.0f;
        for (int k = 0; k < HH; k++) acc += g_G[tid*HH + k];
        g_rs[tid] = acc;
    }
    if (bid == 0) {                 // ALL 512 threads enter: uniform barriers
        const int CH = 9;           // 256*9 = 2304 >= 2197
        int base = tid*CH, sum = 0, loc[CH];
        if (tid < 256) {
            for (int k = 0; k < CH; k++) {
                int c = base + k; int v = (c < NC) ? g_cellCnt[c] : 0;
                loc[k] = v; sum += v;
            }
            spart[tid] = sum;
        }
        __syncthreads();
        if (tid == 0) {
            int acc = 0;
            for (int b = 0; b < 256; b++) { int v = spart[b]; spart[b] = acc; acc += v; }
            g_cellStart[NC] = acc;
        }
        __syncthreads();
        if (tid < 256) {
            int acc = spart[tid];
            for (int k = 0; k < CH; k++) {
                int c = base + k;
                if (c < NC) { g_cellStart[c] = acc; g_cursor[c] = acc; }
                acc += loc[k];
            }
        }
    }
    gridbar(2ULL*NBLK);

    // ---- phase C: scatter pixel ids (GUARDED: gtid < NP) ----
    if (gtid < NP) {
        int slot = atomicAdd(&g_cursor[cellOf(rgb, gtid)], 1);
        g_sidx[slot] = gtid;
    }
    gridbar(3ULL*NBLK);

    // ---- phase D: per-cell sort (determinism) + sorted feature fill ----
    if (gtid < NC) {
        int st = g_cellStart[gtid], en = g_cellStart[gtid+1];
        for (int a = st + 1; a < en; a++) {
            int v = g_sidx[a]; int k = a - 1;
            while (k >= st && g_sidx[k] > v) { g_sidx[k+1] = g_sidx[k]; k--; }
            g_sidx[k+1] = v;
        }
        for (int sl = st; sl < en; sl++) {
            int pp = g_sidx[sl];
            int y = pp >> 7, x = pp & 127;
            g_sfA[sl] = make_float4((float)x * INV_TA, (float)y * INV_TA,
                                    rgb[3*pp] * INV_TB, rgb[3*pp+1] * INV_TB);
            g_sfB[sl] = make_float2(rgb[3*pp+2] * INV_TB, __int_as_float(pp));
        }
    }
    gridbar(4ULL*NBLK);

    // ---- phase E: ELL build, warp per pixel (2048 warps x 8 pixels) ----
    {
        int gwarp = (gtid >> 5);                // 0..2047
        int lane  = tid & 31;
        for (int i = 0; i < 8; i++) {
            int pp = gwarp * 8 + i;             // 0..16383
            int y = pp >> 7, x = pp & 127;
            float f0 = (float)x * INV_TA;
            float f1 = (float)y * INV_TA;
            float f2 = rgb[3*pp]   * INV_TB;
            float f3 = rgb[3*pp+1] * INV_TB;
            float f4 = rgb[3*pp+2] * INV_TB;
            int c0 = clampCell(rgb[3*pp]);
            int c1 = clampCell(rgb[3*pp+1]);
            int c2 = clampCell(rgb[3*pp+2]);

            int cnt = 0; float norm = 0.0f;
            for (int dz = -1; dz <= 1; dz++) {
                int cz = c2 + dz; if (cz < 0 || cz >= GC) continue;
                for (int dy = -1; dy <= 1; dy++) {
                    int cy = c1 + dy; if (cy < 0 || cy >= GC) continue;
                    for (int dx = -1; dx <= 1; dx++) {
                        int cx = c0 + dx; if (cx < 0 || cx >= GC) continue;
                        int cell = (cz*GC + cy)*GC + cx;
                        int st = g_cellStart[cell], en = g_cellStart[cell+1];
                        for (int s0 = st; s0 < en; s0 += 32) {
                            int sl = s0 + lane;
                            bool keep = false; float val = 0.0f; int jdx = 0;
                            if (sl < en) {
                                float4 fA = g_sfA[sl];
                                float2 fB = g_sfB[sl];
                                float d0 = f0-fA.x, d1 = f1-fA.y, d2 = f2-fA.z,
                                      d3 = f3-fA.w, d4 = f4-fB.x;
                                float e = 0.5f*(d0*d0+d1*d1+d2*d2+d3*d3+d4*d4);
                                if (e < ETH) { keep = true; val = __expf(-e);
                                               jdx = __float_as_int(fB.y); }
                            }
                            unsigned m = __ballot_sync(0xffffffffu, keep);
                            if (keep) {
                                int off = cnt + __popc(m & ((1u << lane) - 1u));
                                if (off < CAP) {
                                    g_ell[off*NP + pp] = make_float2(val, __int_as_float(jdx));
                                    norm += val;
                                }
                            }
                            cnt += __popc(m);
                        }
                    }
                }
            }
            if (cnt > CAP) cnt = CAP;
            for (int o = 16; o > 0; o >>= 1)
                norm += __shfl_xor_sync(0xffffffffu, norm, o);
            if (lane == 0) { g_ellCnt[pp] = cnt; g_blNorm[pp] = norm; }
        }
    }
    gridbar(5ULL*NBLK);

    // ---- prologue: per-row constants + sm(U) + row pass into buffer 0 ----
    float u0 = 0.f, u1 = 0.f, invn = 0.f, bln = 1.f;
    if (tid < HH) {
        sg[t]   = g_G[r*HH + t];
        scnt[t] = g_ellCnt[p];
        invn    = 1.0f / (g_rs[r] * g_rs[t]);
        bln     = g_blNorm[p];
        u0 = U[2*p]; u1 = U[2*p+1];
        float sm = 1.0f / (1.0f + __expf(u1 - u0));
        g_sm0[p] = sm;
        s[t] = sm;
    }
    float ws0 = Ws[0], ws1 = Ws[1], ws2 = Ws[2], ws3 = Ws[3];
    float wb0 = Wb[0], wb1 = Wb[1], wb2 = Wb[2], wb3 = Wb[3];
    float cm0 = Cm[0], cm1 = Cm[1], cm2 = Cm[2], cm3 = Cm[3];
    __syncthreads();
    {   // row pass: T[r,t] = sum_k s[k] * G[k,t], split 4 ways
        float acc = 0.0f;
        int k0 = qq * 32;
        #pragma unroll 8
        for (int k = k0; k < k0 + 32; k++) acc += s[k] * g_G[k*HH + t];
        red1[tid] = acc;
        __syncthreads();
        if (tid < HH) g_T[p] = red1[t] + red1[t+128] + red1[t+256] + red1[t+384];
    }
    gridbar(6ULL*NBLK);

    // ---- 10 mean-field iterations, one grid barrier each (double-buffered) --
    float q0 = u0, q1 = u1;
    for (int it = 0; it < 10; it++) {
        int cur = it & 1, nxt = cur ^ 1;

        // column pass partial: sp[r,t] = sum_j sg[j] * T[j,t]
        {
            const float* Tc = g_T + cur*NP;
            float acc = 0.0f;
            int j0 = qq * 32;
            #pragma unroll 8
            for (int j = j0; j < j0 + 32; j++) acc += sg[j] * Tc[j*HH + t];
            red1[tid] = acc;
        }
        // bilateral SpMV partial: slots qq, qq+4, ...
        {
            const float* smc = g_sm0 + cur*NP;
            int cnt = scnt[t];
            float acc = 0.0f;
            for (int k = qq; k < cnt; k += 4) {
                float2 e = g_ell[k*NP + p];
                acc += e.x * smc[__float_as_int(e.y)];
            }
            red2[tid] = acc;
        }
        __syncthreads();

        if (tid < HH) {
            float sp = (red1[t] + red1[t+128] + red1[t+256] + red1[t+384]) * invn;
            float bl = (red2[t] + red2[t+128] + red2[t+256] + red2[t+384]) / bln;
            float sp1 = 1.0f - sp, bl1 = 1.0f - bl;
            float mp0 = ws0*sp + ws1*sp1 + wb0*bl + wb1*bl1;
            float mp1 = ws2*sp + ws3*sp1 + wb2*bl + wb3*bl1;
            q0 = u0 - (cm0*mp0 + cm1*mp1);
            q1 = u1 - (cm2*mp0 + cm3*mp1);
            if (it < 9) {
                float sm = 1.0f / (1.0f + __expf(q1 - q0));
                g_sm0[nxt*NP + p] = sm;
                s[t] = sm;
            }
        }
        if (it < 9) {
            __syncthreads();
            float acc = 0.0f;
            int k0 = qq * 32;
            #pragma unroll 8
            for (int k = k0; k < k0 + 32; k++) acc += s[k] * g_G[k*HH + t];
            red1[tid] = acc;
            __syncthreads();
            if (tid < HH)
                g_T[nxt*NP + p] = red1[t] + red1[t+128] + red1[t+256] + red1[t+384];
            gridbar((unsigned long long)(7 + it) * NBLK);
        }
    }

    if (tid < HH) {
        out[2*p]   = q0;
        out[2*p+1] = q1;
    }
}

// ---------------- launch ----------------
extern "C" void kernel_launch(void* const* d_in, const int* in_sizes, int n_in,
                              void* d_out, int out_size) {
    const float* U   = (const float*)d_in[0];
    const float* rgb = (const float*)d_in[1];
    const float* Ws  = (const float*)d_in[2];
    const float* Wb  = (const float*)d_in[3];
    const float* Cm  = (const float*)d_in[4];
    float* out = (float*)d_out;

    k_zero<<<(NC + 511)/512, 512>>>();
    k_crf <<<NBLK, NTHR>>>(U, rgb, Ws, Wb, Cm, out);
}

// round 7
// speedup vs baseline: 2.5153x; 1.5028x over previous
#include <cuda_runtime.h>
#include <cstdint>

#define HH 128
#define NP 16384            // HH*HH pixels
#define GC 13               // color-grid cells per axis
#define NC (GC*GC*GC)       // 2197 cells
#define CELLW 21.0f
#define CAP 64              // max kept neighbors per pixel
#define ETH 16.0f           // keep K >= exp(-16); dropped tail ~2e-7
#define INV_TA (1.0f/160.0f)
#define INV_TB (1.0f/3.0f)
#define NBLK 128            // grid blocks (< 148 SMs -> co-resident)
#define NTHR 512            // threads per block (16 warps)
// spatial Gaussian band: w(d) = exp(-d^2/18), support |d| <= 16 (w(16)~6.7e-7)

// ---------------- device scratch ----------------
__device__ int    g_cellCnt[NC];
__device__ int    g_cellStart[NC+1];
__device__ int    g_cursor[NC];
__device__ int    g_sidx[NP];
__device__ float4 g_sfA[NP];
__device__ float2 g_sfB[NP];
__device__ float2 g_ell[CAP*NP];     // slot-major: (.x=K, .y=bitcast idx)
__device__ int    g_ellCnt[NP];
__device__ float  g_blNorm[NP];
__device__ float  g_sm0[2*NP];       // double-buffered softmax ch0
__device__ float  g_T[2*NP];         // double-buffered spatial row-pass
__device__ unsigned long long g_barCnt;

// ---- grid barrier: fence + atomic arrival, volatile-load polling ---------
__device__ __forceinline__ void gridbar(unsigned long long target) {
    __syncthreads();
    if (threadIdx.x == 0) {
        __threadfence();
        atomicAdd(&g_barCnt, 1ULL);
        volatile unsigned long long* c = &g_barCnt;
        while (*c < target) { }
        __threadfence();
    }
    __syncthreads();
}

__device__ __forceinline__ int clampCell(float v) {
    int c = (int)(v * (1.0f/CELLW));
    return c < 0 ? 0 : (c > GC-1 ? GC-1 : c);
}
__device__ __forceinline__ int cellOf(const float* __restrict__ rgb, int p) {
    return (clampCell(rgb[3*p+2])*GC + clampCell(rgb[3*p+1]))*GC + clampCell(rgb[3*p]);
}

__global__ void k_zero() {
    int t = blockIdx.x * blockDim.x + threadIdx.x;
    if (t == 0) g_barCnt = 0ULL;
    if (t < NC) g_cellCnt[t] = 0;
}

// ---------------- mega-kernel ----------------
__global__ void __launch_bounds__(NTHR, 1)
k_crf(const float* __restrict__ U, const float* __restrict__ rgb,
      const float* __restrict__ Ws, const float* __restrict__ Wb,
      const float* __restrict__ Cm, float* __restrict__ out) {
    const int tid  = threadIdx.x;
    const int bid  = blockIdx.x;
    const int gtid = bid * NTHR + tid;          // 0..65535
    const int t    = tid & 127;
    const int qq   = tid >> 7;                  // quarter 0..3
    const int r    = bid;
    const int p    = r * HH + t;

    __shared__ float s[HH];
    __shared__ float red1[NTHR];
    __shared__ float red2[NTHR];
    __shared__ int   scnt[HH];
    __shared__ int   spart[256];

    // per-thread band weights: offsets d_i = qq*8 - 16 + i, i=0..7
    float wreg[8];
    #pragma unroll
    for (int i = 0; i < 8; i++) {
        int d = qq*8 - 16 + i;
        wreg[i] = __expf(-(float)(d*d) * (1.0f/18.0f));
    }

    // ---- phase A: per-cell counts ----
    if (gtid < NP) atomicAdd(&g_cellCnt[cellOf(rgb, gtid)], 1);
    gridbar(1ULL*NBLK);

    // ---- phase B: exclusive scan (block 0, uniform barriers) ----
    if (bid == 0) {
        const int CH = 9;           // 256*9 = 2304 >= 2197
        int base = tid*CH, sum = 0, loc[CH];
        if (tid < 256) {
            for (int k = 0; k < CH; k++) {
                int c = base + k; int v = (c < NC) ? g_cellCnt[c] : 0;
                loc[k] = v; sum += v;
            }
            spart[tid] = sum;
        }
        __syncthreads();
        if (tid == 0) {
            int acc = 0;
            for (int b = 0; b < 256; b++) { int v = spart[b]; spart[b] = acc; acc += v; }
            g_cellStart[NC] = acc;
        }
        __syncthreads();
        if (tid < 256) {
            int acc = spart[tid];
            for (int k = 0; k < CH; k++) {
                int c = base + k;
                if (c < NC) { g_cellStart[c] = acc; g_cursor[c] = acc; }
                acc += loc[k];
            }
        }
    }
    gridbar(2ULL*NBLK);

    // ---- phase C: scatter pixel ids ----
    if (gtid < NP) {
        int slot = atomicAdd(&g_cursor[cellOf(rgb, gtid)], 1);
        g_sidx[slot] = gtid;
    }
    gridbar(3ULL*NBLK);

    // ---- phase D1: per-cell insertion sort (determinism) ----
    if (gtid < NC) {
        int st = g_cellStart[gtid], en = g_cellStart[gtid+1];
        for (int a = st + 1; a < en; a++) {
            int v = g_sidx[a]; int k = a - 1;
            while (k >= st && g_sidx[k] > v) { g_sidx[k+1] = g_sidx[k]; k--; }
            g_sidx[k+1] = v;
        }
    }
    gridbar(4ULL*NBLK);

    // ---- phase D2: slot-parallel feature fill (16384 threads) ----
    if (gtid < NP) {
        int pp = g_sidx[gtid];
        int y = pp >> 7, x = pp & 127;
        g_sfA[gtid] = make_float4((float)x * INV_TA, (float)y * INV_TA,
                                  rgb[3*pp] * INV_TB, rgb[3*pp+1] * INV_TB);
        g_sfB[gtid] = make_float2(rgb[3*pp+2] * INV_TB, __int_as_float(pp));
    }
    gridbar(5ULL*NBLK);

    // ---- phase E: ELL build, warp per pixel, 9 contiguous ranges ----
    {
        int gwarp = (gtid >> 5);                // 0..2047
        int lane  = tid & 31;
        for (int i = 0; i < 8; i++) {
            int pp = gwarp * 8 + i;             // 0..16383
            int y = pp >> 7, x = pp & 127;
            float f0 = (float)x * INV_TA;
            float f1 = (float)y * INV_TA;
            float f2 = rgb[3*pp]   * INV_TB;
            float f3 = rgb[3*pp+1] * INV_TB;
            float f4 = rgb[3*pp+2] * INV_TB;
            int c0 = clampCell(rgb[3*pp]);
            int c1 = clampCell(rgb[3*pp+1]);
            int c2 = clampCell(rgb[3*pp+2]);
            int xlo = c0 > 0      ? c0 - 1 : 0;
            int xhi = c0 < GC - 1 ? c0 + 1 : GC - 1;

            int cnt = 0; float norm = 0.0f;
            for (int dz = -1; dz <= 1; dz++) {
                int cz = c2 + dz; if (cz < 0 || cz >= GC) continue;
                for (int dy = -1; dy <= 1; dy++) {
                    int cy = c1 + dy; if (cy < 0 || cy >= GC) continue;
                    int base = (cz*GC + cy)*GC;
                    int st = g_cellStart[base + xlo];
                    int en = g_cellStart[base + xhi + 1];   // 3 consecutive cells
                    for (int s0 = st; s0 < en; s0 += 32) {
                        int sl = s0 + lane;
                        bool keep = false; float val = 0.0f; int jdx = 0;
                        if (sl < en) {
                            float4 fA = g_sfA[sl];
                            float2 fB = g_sfB[sl];
                            float d0 = f0-fA.x, d1 = f1-fA.y, d2 = f2-fA.z,
                                  d3 = f3-fA.w, d4 = f4-fB.x;
                            float e = 0.5f*(d0*d0+d1*d1+d2*d2+d3*d3+d4*d4);
                            if (e < ETH) { keep = true; val = __expf(-e);
                                           jdx = __float_as_int(fB.y); }
                        }
                        unsigned m = __ballot_sync(0xffffffffu, keep);
                        if (keep) {
                            int off = cnt + __popc(m & ((1u << lane) - 1u));
                            if (off < CAP) {
                                g_ell[off*NP + pp] = make_float2(val, __int_as_float(jdx));
                                norm += val;
                            }
                        }
                        cnt += __popc(m);
                    }
                }
            }
            if (cnt > CAP) cnt = CAP;
            for (int o = 16; o > 0; o >>= 1)
                norm += __shfl_xor_sync(0xffffffffu, norm, o);
            if (lane == 0) { g_ellCnt[pp] = cnt; g_blNorm[pp] = norm; }
        }
    }
    gridbar(6ULL*NBLK);

    // ---- prologue: constants + sm(U) + band row pass into buffer 0 ----
    float u0 = 0.f, u1 = 0.f, invn = 0.f, bln = 1.f;
    if (tid < HH) {
        scnt[t] = g_ellCnt[p];
        // band norm: rs(x) = sum_{d=-16..15, in-range} w(|d|)
        float rsr = 0.f, rst = 0.f;
        #pragma unroll
        for (int d = -16; d < 16; d++) {
            float w = __expf(-(float)(d*d) * (1.0f/18.0f));
            if ((unsigned)(r + d) < (unsigned)HH) rsr += w;
            if ((unsigned)(t + d) < (unsigned)HH) rst += w;
        }
        invn = 1.0f / (rsr * rst);
        bln  = g_blNorm[p];
        u0 = U[2*p]; u1 = U[2*p+1];
        float sm = 1.0f / (1.0f + __expf(u1 - u0));
        g_sm0[p] = sm;
        s[t] = sm;
    }
    float ws0 = Ws[0], ws1 = Ws[1], ws2 = Ws[2], ws3 = Ws[3];
    float wb0 = Wb[0], wb1 = Wb[1], wb2 = Wb[2], wb3 = Wb[3];
    float cm0 = Cm[0], cm1 = Cm[1], cm2 = Cm[2], cm3 = Cm[3];
    __syncthreads();
    {   // band row pass: T[r,t] = sum_d s[t+d]*w(|d|), quarter qq does 8 taps
        float acc = 0.0f;
        #pragma unroll
        for (int i = 0; i < 8; i++) {
            int k = t + qq*8 - 16 + i;
            if ((unsigned)k < (unsigned)HH) acc += s[k] * wreg[i];
        }
        red1[tid] = acc;
        __syncthreads();
        if (tid < HH) g_T[p] = red1[t] + red1[t+128] + red1[t+256] + red1[t+384];
    }
    gridbar(7ULL*NBLK);

    // ---- 10 mean-field iterations ----
    float q0 = u0, q1 = u1;
    for (int it = 0; it < 10; it++) {
        int cur = it & 1, nxt = cur ^ 1;

        // band column pass partial: sp[r,t] = sum_d w(|d|)*T[r+d,t]
        {
            const float* Tc = g_T + cur*NP;
            float acc = 0.0f;
            #pragma unroll
            for (int i = 0; i < 8; i++) {
                int j = r + qq*8 - 16 + i;
                if ((unsigned)j < (unsigned)HH) acc += wreg[i] * Tc[j*HH + t];
            }
            red1[tid] = acc;
        }
        // bilateral SpMV partial: slots qq, qq+4, ...
        {
            const float* smc = g_sm0 + cur*NP;
            int cnt = scnt[t];
            float acc = 0.0f;
            for (int k = qq; k < cnt; k += 4) {
                float2 e = g_ell[k*NP + p];
                acc += e.x * smc[__float_as_int(e.y)];
            }
            red2[tid] = acc;
        }
        __syncthreads();

        if (tid < HH) {
            float sp = (red1[t] + red1[t+128] + red1[t+256] + red1[t+384]) * invn;
            float bl = (red2[t] + red2[t+128] + red2[t+256] + red2[t+384]) / bln;
            float sp1 = 1.0f - sp, bl1 = 1.0f - bl;
            float mp0 = ws0*sp + ws1*sp1 + wb0*bl + wb1*bl1;
            float mp1 = ws2*sp + ws3*sp1 + wb2*bl + wb3*bl1;
            q0 = u0 - (cm0*mp0 + cm1*mp1);
            q1 = u1 - (cm2*mp0 + cm3*mp1);
            if (it < 9) {
                float sm = 1.0f / (1.0f + __expf(q1 - q0));
                g_sm0[nxt*NP + p] = sm;
                s[t] = sm;
            }
        }
        if (it < 9) {
            __syncthreads();
            float acc = 0.0f;
            #pragma unroll
            for (int i = 0; i < 8; i++) {
                int k = t + qq*8 - 16 + i;
                if ((unsigned)k < (unsigned)HH) acc += s[k] * wreg[i];
            }
            red1[tid] = acc;
            __syncthreads();
            if (tid < HH)
                g_T[nxt*NP + p] = red1[t] + red1[t+128] + red1[t+256] + red1[t+384];
            gridbar((unsigned long long)(8 + it) * NBLK);
        }
    }

    if (tid < HH) {
        out[2*p]   = q0;
        out[2*p+1] = q1;
    }
}

// ---------------- launch ----------------
extern "C" void kernel_launch(void* const* d_in, const int* in_sizes, int n_in,
                              void* d_out, int out_size) {
    const float* U   = (const float*)d_in[0];
    const float* rgb = (const float*)d_in[1];
    const float* Ws  = (const float*)d_in[2];
    const float* Wb  = (const float*)d_in[3];
    const float* Cm  = (const float*)d_in[4];
    float* out = (float*)d_out;

    k_zero<<<(NC + 511)/512, 512>>>();
    k_crf <<<NBLK, NTHR>>>(U, rgb, Ws, Wb, Cm, out);
}

// round 8
// speedup vs baseline: 2.9110x; 1.1573x over previous
#include <cuda_runtime.h>
#include <cstdint>

#define HH 128
#define NP 16384            // HH*HH pixels
#define GC 13               // color-grid cells per axis
#define NC (GC*GC*GC)       // 2197 cells
#define CELLW 21.0f
#define CAP 64              // max kept neighbors per pixel
#define ETH 16.0f           // keep K >= exp(-16); dropped tail ~2e-7
#define INV_TA (1.0f/160.0f)
#define INV_TB (1.0f/3.0f)
#define NBLK 128            // grid blocks (< 148 SMs -> co-resident)
#define NTHR 512            // threads per block (16 warps)
// spatial Gaussian band: w(d) = exp(-d^2/18), support |d| <= 16 (w(16)~6.7e-7)

// ---------------- device scratch ----------------
__device__ int    g_cellCnt[NC];
__device__ int    g_cellStart[NC+1];
__device__ int    g_cursor[NC];
__device__ int    g_sidx[NP];
__device__ float4 g_sfA[NP];
__device__ float2 g_sfB[NP];
__device__ float2 g_ell[CAP*NP];     // slot-major: (.x=K, .y=bitcast idx)
__device__ int    g_ellCnt[NP];
__device__ float  g_blNorm[NP];
__device__ float  g_sm0[2*NP];       // double-buffered softmax ch0
__device__ float  g_T[2*NP];         // double-buffered spatial row-pass
__device__ unsigned long long g_barCnt;

// ---- grid barrier: fence + atomic arrival, volatile-load polling ---------
__device__ __forceinline__ void gridbar(unsigned long long target) {
    __syncthreads();
    if (threadIdx.x == 0) {
        __threadfence();
        atomicAdd(&g_barCnt, 1ULL);
        volatile unsigned long long* c = &g_barCnt;
        while (*c < target) { }
        __threadfence();
    }
    __syncthreads();
}

__device__ __forceinline__ int clampCell(float v) {
    int c = (int)(v * (1.0f/CELLW));
    return c < 0 ? 0 : (c > GC-1 ? GC-1 : c);
}
__device__ __forceinline__ int cellOf(const float* __restrict__ rgb, int p) {
    return (clampCell(rgb[3*p+2])*GC + clampCell(rgb[3*p+1]))*GC + clampCell(rgb[3*p]);
}

__global__ void k_zero() {
    int t = blockIdx.x * blockDim.x + threadIdx.x;
    if (t == 0) g_barCnt = 0ULL;
    if (t < NC) g_cellCnt[t] = 0;
}

// ---------------- mega-kernel ----------------
__global__ void __launch_bounds__(NTHR, 1)
k_crf(const float* __restrict__ U, const float* __restrict__ rgb,
      const float* __restrict__ Ws, const float* __restrict__ Wb,
      const float* __restrict__ Cm, float* __restrict__ out) {
    const int tid  = threadIdx.x;
    const int bid  = blockIdx.x;
    const int gtid = bid * NTHR + tid;          // 0..65535
    const int t    = tid & 127;
    const int qq   = tid >> 7;                  // quarter 0..3
    const int r    = bid;
    const int p    = r * HH + t;

    __shared__ float s[HH];
    __shared__ float red1[NTHR];
    __shared__ float red2[NTHR];
    __shared__ int   scnt[HH];
    __shared__ int   spart[256];

    // per-thread band weights: offsets d_i = qq*8 - 16 + i, i=0..7
    float wreg[8];
    #pragma unroll
    for (int i = 0; i < 8; i++) {
        int d = qq*8 - 16 + i;
        wreg[i] = __expf(-(float)(d*d) * (1.0f/18.0f));
    }

    // ---- phase A: per-cell counts ----
    if (gtid < NP) atomicAdd(&g_cellCnt[cellOf(rgb, gtid)], 1);
    gridbar(1ULL*NBLK);

    // ---- phase B: exclusive scan (block 0, uniform barriers) ----
    if (bid == 0) {
        const int CH = 9;           // 256*9 = 2304 >= 2197
        int base = tid*CH, sum = 0, loc[CH];
        if (tid < 256) {
            for (int k = 0; k < CH; k++) {
                int c = base + k; int v = (c < NC) ? g_cellCnt[c] : 0;
                loc[k] = v; sum += v;
            }
            spart[tid] = sum;
        }
        __syncthreads();
        if (tid == 0) {
            int acc = 0;
            for (int b = 0; b < 256; b++) { int v = spart[b]; spart[b] = acc; acc += v; }
            g_cellStart[NC] = acc;
        }
        __syncthreads();
        if (tid < 256) {
            int acc = spart[tid];
            for (int k = 0; k < CH; k++) {
                int c = base + k;
                if (c < NC) { g_cellStart[c] = acc; g_cursor[c] = acc; }
                acc += loc[k];
            }
        }
    }
    gridbar(2ULL*NBLK);

    // ---- phase C: scatter pixel ids ----
    if (gtid < NP) {
        int slot = atomicAdd(&g_cursor[cellOf(rgb, gtid)], 1);
        g_sidx[slot] = gtid;
    }
    gridbar(3ULL*NBLK);

    // ---- phase D1: per-cell insertion sort (determinism) ----
    if (gtid < NC) {
        int st = g_cellStart[gtid], en = g_cellStart[gtid+1];
        for (int a = st + 1; a < en; a++) {
            int v = g_sidx[a]; int k = a - 1;
            while (k >= st && g_sidx[k] > v) { g_sidx[k+1] = g_sidx[k]; k--; }
            g_sidx[k+1] = v;
        }
    }
    gridbar(4ULL*NBLK);

    // ---- phase D2: slot-parallel feature fill (16384 threads) ----
    if (gtid < NP) {
        int pp = g_sidx[gtid];
        int y = pp >> 7, x = pp & 127;
        g_sfA[gtid] = make_float4((float)x * INV_TA, (float)y * INV_TA,
                                  rgb[3*pp] * INV_TB, rgb[3*pp+1] * INV_TB);
        g_sfB[gtid] = make_float2(rgb[3*pp+2] * INV_TB, __int_as_float(pp));
    }
    gridbar(5ULL*NBLK);

    // ---- phase E: ELL build, warp per pixel, prefetched range bounds ----
    {
        int gwarp = (gtid >> 5);                // 0..2047
        int lane  = tid & 31;
        for (int i = 0; i < 8; i++) {
            int pp = gwarp * 8 + i;             // 0..16383
            int y = pp >> 7, x = pp & 127;
            float f0 = (float)x * INV_TA;
            float f1 = (float)y * INV_TA;
            float f2 = rgb[3*pp]   * INV_TB;
            float f3 = rgb[3*pp+1] * INV_TB;
            float f4 = rgb[3*pp+2] * INV_TB;
            int c0 = clampCell(rgb[3*pp]);
            int c1 = clampCell(rgb[3*pp+1]);
            int c2 = clampCell(rgb[3*pp+2]);
            int xlo = c0 > 0      ? c0 - 1 : 0;
            int xhi = c0 < GC - 1 ? c0 + 1 : GC - 1;

            // prefetch all 9 (st,en) range bounds with full MLP
            int stA[9], enA[9];
            #pragma unroll
            for (int rr = 0; rr < 9; rr++) {
                int dz = rr / 3 - 1, dy = rr % 3 - 1;
                int cz = c2 + dz, cy = c1 + dy;
                bool ok = (cz >= 0) && (cz < GC) && (cy >= 0) && (cy < GC);
                int base = ok ? (cz*GC + cy)*GC : 0;
                int lo = ok ? g_cellStart[base + xlo]     : 0;
                int hi = ok ? g_cellStart[base + xhi + 1] : 0;
                stA[rr] = lo; enA[rr] = hi;
            }

            int cnt = 0; float norm = 0.0f;
            #pragma unroll
            for (int rr = 0; rr < 9; rr++) {
                for (int s0 = stA[rr]; s0 < enA[rr]; s0 += 32) {
                    int sl = s0 + lane;
                    bool keep = false; float val = 0.0f; int jdx = 0;
                    if (sl < enA[rr]) {
                        float4 fA = g_sfA[sl];
                        float2 fB = g_sfB[sl];
                        float d0 = f0-fA.x, d1 = f1-fA.y, d2 = f2-fA.z,
                              d3 = f3-fA.w, d4 = f4-fB.x;
                        float e = 0.5f*(d0*d0+d1*d1+d2*d2+d3*d3+d4*d4);
                        if (e < ETH) { keep = true; val = __expf(-e);
                                       jdx = __float_as_int(fB.y); }
                    }
                    unsigned m = __ballot_sync(0xffffffffu, keep);
                    if (keep) {
                        int off = cnt + __popc(m & ((1u << lane) - 1u));
                        if (off < CAP) {
                            g_ell[off*NP + pp] = make_float2(val, __int_as_float(jdx));
                            norm += val;
                        }
                    }
                    cnt += __popc(m);
                }
            }
            if (cnt > CAP) cnt = CAP;
            for (int o = 16; o > 0; o >>= 1)
                norm += __shfl_xor_sync(0xffffffffu, norm, o);
            if (lane == 0) { g_ellCnt[pp] = cnt; g_blNorm[pp] = norm; }
        }
    }
    gridbar(6ULL*NBLK);

    // ---- prologue: constants + sm(U) + band row pass into buffer 0 ----
    float u0 = 0.f, u1 = 0.f, invn = 0.f, bln = 1.f;
    if (tid < HH) {
        scnt[t] = g_ellCnt[p];
        float rsr = 0.f, rst = 0.f;
        #pragma unroll
        for (int d = -16; d < 16; d++) {
            float w = __expf(-(float)(d*d) * (1.0f/18.0f));
            if ((unsigned)(r + d) < (unsigned)HH) rsr += w;
            if ((unsigned)(t + d) < (unsigned)HH) rst += w;
        }
        invn = 1.0f / (rsr * rst);
        bln  = g_blNorm[p];
        u0 = U[2*p]; u1 = U[2*p+1];
        float sm = 1.0f / (1.0f + __expf(u1 - u0));
        g_sm0[p] = sm;
        s[t] = sm;
    }
    float ws0 = Ws[0], ws1 = Ws[1], ws2 = Ws[2], ws3 = Ws[3];
    float wb0 = Wb[0], wb1 = Wb[1], wb2 = Wb[2], wb3 = Wb[3];
    float cm0 = Cm[0], cm1 = Cm[1], cm2 = Cm[2], cm3 = Cm[3];
    __syncthreads();
    {   // band row pass: quarter qq does 8 taps
        float acc = 0.0f;
        #pragma unroll
        for (int i = 0; i < 8; i++) {
            int k = t + qq*8 - 16 + i;
            if ((unsigned)k < (unsigned)HH) acc += s[k] * wreg[i];
        }
        red1[tid] = acc;
        __syncthreads();
        if (tid < HH) g_T[p] = red1[t] + red1[t+128] + red1[t+256] + red1[t+384];
    }
    gridbar(7ULL*NBLK);

    // ---- 10 mean-field iterations ----
    float q0 = u0, q1 = u1;
    for (int it = 0; it < 10; it++) {
        int cur = it & 1, nxt = cur ^ 1;

        // band column pass partial (8 taps, addresses independent -> MLP)
        {
            const float* Tc = g_T + cur*NP;
            float acc = 0.0f;
            #pragma unroll
            for (int i = 0; i < 8; i++) {
                int j = r + qq*8 - 16 + i;
                if ((unsigned)j < (unsigned)HH) acc += wreg[i] * Tc[j*HH + t];
            }
            red1[tid] = acc;
        }
        // bilateral SpMV partial: fixed-trip predicated prefetch (MLP=16)
        {
            const float* smc = g_sm0 + cur*NP;
            int cnt = scnt[t];
            float2 ev[16];
            #pragma unroll
            for (int i = 0; i < 16; i++) {
                int k = qq + 4*i;
                ev[i] = (k < cnt) ? g_ell[k*NP + p]
                                  : make_float2(0.0f, __int_as_float(0));
            }
            float acc = 0.0f;
            #pragma unroll
            for (int i = 0; i < 16; i++)
                acc += ev[i].x * smc[__float_as_int(ev[i].y)];
            red2[tid] = acc;
        }
        __syncthreads();

        if (tid < HH) {
            float sp = (red1[t] + red1[t+128] + red1[t+256] + red1[t+384]) * invn;
            float bl = (red2[t] + red2[t+128] + red2[t+256] + red2[t+384]) / bln;
            float sp1 = 1.0f - sp, bl1 = 1.0f - bl;
            float mp0 = ws0*sp + ws1*sp1 + wb0*bl + wb1*bl1;
            float mp1 = ws2*sp + ws3*sp1 + wb2*bl + wb3*bl1;
            q0 = u0 - (cm0*mp0 + cm1*mp1);
            q1 = u1 - (cm2*mp0 + cm3*mp1);
            if (it < 9) {
                float sm = 1.0f / (1.0f + __expf(q1 - q0));
                g_sm0[nxt*NP + p] = sm;
                s[t] = sm;
            }
        }
        if (it < 9) {
            __syncthreads();
            float acc = 0.0f;
            #pragma unroll
            for (int i = 0; i < 8; i++) {
                int k = t + qq*8 - 16 + i;
                if ((unsigned)k < (unsigned)HH) acc += s[k] * wreg[i];
            }
            red1[tid] = acc;
            __syncthreads();
            if (tid < HH)
                g_T[nxt*NP + p] = red1[t] + red1[t+128] + red1[t+256] + red1[t+384];
            gridbar((unsigned long long)(8 + it) * NBLK);
        }
    }

    if (tid < HH) {
        out[2*p]   = q0;
        out[2*p+1] = q1;
    }
}

// ---------------- launch ----------------
extern "C" void kernel_launch(void* const* d_in, const int* in_sizes, int n_in,
                              void* d_out, int out_size) {
    const float* U   = (const float*)d_in[0];
    const float* rgb = (const float*)d_in[1];
    const float* Ws  = (const float*)d_in[2];
    const float* Wb  = (const float*)d_in[3];
    const float* Cm  = (const float*)d_in[4];
    float* out = (float*)d_out;

    k_zero<<<(NC + 511)/512, 512>>>();
    k_crf <<<NBLK, NTHR>>>(U, rgb, Ws, Wb, Cm, out);
}